// round 14
// baseline (speedup 1.0000x reference)
#include <cuda_runtime.h>
#include <cuda_bf16.h>

#define HIDDEN 64
#define N_POS 32

// embeddings: rows 0..31 = video positions, rows 32..63 = patches
__device__ float g_emb[64][HIDDEN];
__device__ int   g_count = 0;   // arrival ticket counter (reset by last block)

// ---------------------------------------------------------------------------
// Fused kernel: 128 blocks x 320 threads (best-measured config, R8 family).
//  Phase 1 (all blocks): half the output channels of conv(4->64,3x3,SAME)
//                        +ReLU+avgpool for one image. blockIdx: img*2+half.
//                        warp = row, lane = oc; staged smem loads (R8-proven).
//  Arrival: last block to take a ticket proceeds into phase 2 (no spin).
//  Phase 2 (last block): scores+rank (register/shfl) -> greedy -> d_out.
// ---------------------------------------------------------------------------
__global__ __launch_bounds__(320)
void fused_matcher_kernel(const float* __restrict__ v_latent,
                          const float* __restrict__ p_tensor,
                          const float* __restrict__ v_w,
                          const float* __restrict__ v_b,
                          const float* __restrict__ p_w,
                          const float* __restrict__ p_b,
                          float* __restrict__ out)
{
    // 16B alignment REQUIRED: rows are read below as float2 (LDS.64).
    __shared__ __align__(16) float xs[4][12][10];  // zero-padded input
    __shared__ float ws[32 * 37];       // 32 oc x 36 weights, stride 37 (bank-free)
    __shared__ float psum[10][32];      // per-row partial sums
    __shared__ int   s_ticket;
    // match-phase smem (last block only)
    __shared__ float4 pe4[32 * 17];     // patch emb, 68-float row stride
    __shared__ float4 ve4[32 * 17];     // video emb, 68-float row stride
    __shared__ int    pref[32][32];

    const int img  = blockIdx.x >> 1;
    const int half = blockIdx.x & 1;    // which 32 output channels
    const bool is_v = img < 32;
    const float* __restrict__ w    = (is_v ? v_w : p_w) + half * 32 * 36;
    const float* __restrict__ bias = (is_v ? v_b : p_b) + half * 32;
    const int tid  = threadIdx.x;
    const int lane = tid & 31;

    // ---------------- Phase 1: conv + relu + avgpool (R8-proven) ----------
    for (int i = tid; i < 4 * 12 * 10; i += 320)
        ((float*)xs)[i] = 0.0f;
    for (int i = tid; i < 32 * 36; i += 320)
        ws[(i / 36) * 37 + (i % 36)] = w[i];
    __syncthreads();

    // interior: logical x[a][c][e], a=ch(4), c=h(10), e=w(8)
    {
        int i = tid;   // 320 threads == 320 elements
        int e = i & 7;
        int c = (i >> 3) % 10;
        int a = i / 80;
        float val;
        if (is_v) {
            // v_split[pos=b*8+d, a, c, e] = v_latent[a, b, c, d, e]
            int b_ = img >> 3, d = img & 7;
            val = v_latent[(((a * 4 + b_) * 10 + c) * 8 + d) * 8 + e];
        } else {
            val = p_tensor[(img - 32) * 320 + i];
        }
        xs[a][c + 1][e + 1] = val;
    }
    __syncthreads();

    // lane = oc (broadcast xs loads), warp = output row
    const int row = tid >> 5;   // 0..9
    const int oc  = lane;       // 0..31 (local)

    float wr[4][3][3];
#pragma unroll
    for (int ic = 0; ic < 4; ic++)
#pragma unroll
        for (int kh = 0; kh < 3; kh++)
#pragma unroll
            for (int kw = 0; kw < 3; kw++)
                wr[ic][kh][kw] = ws[oc * 37 + (ic * 3 + kh) * 3 + kw];
    const float bb = bias[oc];

    float y[8];
#pragma unroll
    for (int wc = 0; wc < 8; wc++) y[wc] = bb;

    // sliding-window: per (ic,kh) load the 10-float row once (5 x LDS.64).
#pragma unroll
    for (int ic = 0; ic < 4; ic++) {
#pragma unroll
        for (int kh = 0; kh < 3; kh++) {
            const float2* xrow = (const float2*)&xs[ic][row + kh][0];
            float x[10];
#pragma unroll
            for (int t = 0; t < 5; t++) {
                float2 v2 = xrow[t];
                x[2 * t]     = v2.x;
                x[2 * t + 1] = v2.y;
            }
#pragma unroll
            for (int wc = 0; wc < 8; wc++)
#pragma unroll
                for (int kw = 0; kw < 3; kw++)
                    y[wc] = fmaf(x[wc + kw], wr[ic][kh][kw], y[wc]);
        }
    }
    float acc = 0.0f;
#pragma unroll
    for (int wc = 0; wc < 8; wc++)
        acc += fmaxf(y[wc], 0.0f);
    psum[row][oc] = acc;
    __syncthreads();

    if (tid < 32) {
        float s = 0.0f;
#pragma unroll
        for (int r = 0; r < 10; r++)
            s += psum[r][tid];
        g_emb[img][half * 32 + tid] = s * (1.0f / 80.0f);
    }
    __syncthreads();   // stores issued

    // ------------- arrival: last block to arrive runs phase 2 -------------
    if (tid == 0) {
        __threadfence();                       // release our g_emb stores
        s_ticket = atomicAdd(&g_count, 1);     // ticket
    }
    __syncthreads();
    if (s_ticket != 127)
        return;                                 // not last: done

    __threadfence();   // acquire: order g_emb reads after the atomic

    // reset counter for next replay (all 128 adds already observed)
    if (tid == 0) atomicExch(&g_count, 0);

    // ---------------- Phase 2 (last block only): match ----------------
    // load embeddings into padded smem via float4 (bypass L1)
    for (int i = tid; i < 32 * 16; i += 320) {
        int r = i >> 4, c = i & 15;
        ve4[r * 17 + c] = __ldcg((const float4*)&g_emb[r][c * 4]);
        pe4[r * 17 + c] = __ldcg((const float4*)&g_emb[32 + r][c * 4]);
    }
    __syncthreads();

    // scores + stable descending rank, fully in registers.
    // warp w (0..7) handles patches 4w..4w+3; lane = position v.
    const int wid = tid >> 5;
    const unsigned full = 0xffffffffu;
    if (wid < 8) {
        const int v = lane;
#pragma unroll
        for (int pp = 0; pp < 4; pp++) {
            const int p = wid * 4 + pp;
            float s = 0.0f;
#pragma unroll
            for (int i = 0; i < 16; i++) {
                float4 a = pe4[p * 17 + i];   // broadcast within warp
                float4 b = ve4[v * 17 + i];   // conflict-free (stride 17 f4)
                s = fmaf(a.x, b.x, s);
                s = fmaf(a.y, b.y, s);
                s = fmaf(a.z, b.z, s);
                s = fmaf(a.w, b.w, s);
            }
            // rank among the 32 scores of patch p (stable, descending)
            const float my = s;
            int r = 0;
#pragma unroll
            for (int j = 0; j < 32; j++) {
                float o = __shfl_sync(full, s, j);
                r += (o > my) || (o == my && j < v);
            }
            pref[p][r] = v;
        }
    }
    __syncthreads();

    // Greedy, warp 0, lane = pid. Round-sequential reference semantics
    // == per-round min-pid-per-untaken-position (positions never free up).
    // 2 warp collectives per round; uniform taken==full exit
    // (valid: 32 patches, 32 positions -> full <=> all assigned).
    if (tid < 32) {
        const int pid = tid;
        unsigned taken = 0;
        int mypos = -1;
#pragma unroll 1
        for (int round = 0; round < 32; round++) {
            int cand = pref[pid][round];
            bool want = (mypos < 0) && !((taken >> cand) & 1u);
            // wanters key on cand (0..31); non-wanters get unique keys >=32
            unsigned grp = __match_any_sync(full, want ? cand : 32 + pid);
            bool won = want && ((grp & ((1u << pid) - 1u)) == 0u);
            if (won) mypos = cand;
            taken |= __reduce_or_sync(full, won ? (1u << cand) : 0u);
            if (taken == 0xffffffffu) break;   // uniform exit
        }
        out[pid] = (float)mypos;   // float32 output dtype
    }
}

extern "C" void kernel_launch(void* const* d_in, const int* in_sizes, int n_in,
                              void* d_out, int out_size)
{
    // Input identification. p_old_idx is the unique 32-element input:
    //   dict/insertion order: [v_latent, p_tensor, p_old_idx, v_w, v_b, p_w, p_b]
    //   alphabetical order:   [p_b, p_old_idx, p_tensor, p_w, v_b, v_latent, v_w]
    const float *v_latent, *p_tensor, *v_w, *v_b, *p_w, *p_b;
    if (n_in >= 7 && in_sizes[2] == 32) {
        v_latent = (const float*)d_in[0];
        p_tensor = (const float*)d_in[1];
        v_w      = (const float*)d_in[3];
        v_b      = (const float*)d_in[4];
        p_w      = (const float*)d_in[5];
        p_b      = (const float*)d_in[6];
    } else {
        p_b      = (const float*)d_in[0];
        p_tensor = (const float*)d_in[2];
        p_w      = (const float*)d_in[3];
        v_b      = (const float*)d_in[4];
        v_latent = (const float*)d_in[5];
        v_w      = (const float*)d_in[6];
    }
    float* out = (float*)d_out;

    fused_matcher_kernel<<<128, 320>>>(v_latent, p_tensor, v_w, v_b, p_w, p_b, out);
}

// round 15
// speedup vs baseline: 1.1944x; 1.1944x over previous
#include <cuda_runtime.h>
#include <cuda_bf16.h>

#define HIDDEN 64
#define N_POS 32

// embeddings: rows 0..31 = video positions, rows 32..63 = patches
__device__ float g_emb[64][HIDDEN];
__device__ int   g_count = 0;   // self-resetting cross-block arrival counter

// ---------------------------------------------------------------------------
// Fused kernel: 128 blocks x 320 threads.  (verbatim R8 — best measured)
//  Phase 1 (all blocks): half the output channels of conv(4->64,3x3,SAME)
//                        +ReLU+avgpool for one image. blockIdx: img*2+half.
//  Phase 2 (block 0):    scores+rank (register/shfl) -> greedy -> d_out.
// ---------------------------------------------------------------------------
__global__ __launch_bounds__(320)
void fused_matcher_kernel(const float* __restrict__ v_latent,
                          const float* __restrict__ p_tensor,
                          const float* __restrict__ v_w,
                          const float* __restrict__ v_b,
                          const float* __restrict__ p_w,
                          const float* __restrict__ p_b,
                          float* __restrict__ out)
{
    // 16B alignment is REQUIRED: rows are read below as float2 (LDS.64).
    __shared__ __align__(16) float xs[4][12][10];  // zero-padded input
    __shared__ float ws[32 * 37];       // 32 oc x 36 weights, stride 37 (bank-free)
    __shared__ float psum[10][32];      // per-row partial sums
    // match-phase smem (block 0 only)
    __shared__ float4 pe4[32 * 17];     // patch emb, 68-float row stride
    __shared__ float4 ve4[32 * 17];     // video emb, 68-float row stride
    __shared__ int    pref[32][32];

    const int img  = blockIdx.x >> 1;
    const int half = blockIdx.x & 1;    // which 32 output channels
    const bool is_v = img < 32;
    const float* __restrict__ w    = (is_v ? v_w : p_w) + half * 32 * 36;
    const float* __restrict__ bias = (is_v ? v_b : p_b) + half * 32;
    const int tid  = threadIdx.x;
    const int lane = tid & 31;

    // ---------------- Phase 1: conv + relu + avgpool ----------------
    for (int i = tid; i < 4 * 12 * 10; i += 320)
        ((float*)xs)[i] = 0.0f;
    for (int i = tid; i < 32 * 36; i += 320)
        ws[(i / 36) * 37 + (i % 36)] = w[i];
    __syncthreads();

    // interior: logical x[a][c][e], a=ch(4), c=h(10), e=w(8)
    {
        int i = tid;   // 320 threads == 320 elements
        int e = i & 7;
        int c = (i >> 3) % 10;
        int a = i / 80;
        float val;
        if (is_v) {
            // v_split[pos=b*8+d, a, c, e] = v_latent[a, b, c, d, e]
            int b_ = img >> 3, d = img & 7;
            val = v_latent[(((a * 4 + b_) * 10 + c) * 8 + d) * 8 + e];
        } else {
            val = p_tensor[(img - 32) * 320 + i];
        }
        xs[a][c + 1][e + 1] = val;
    }
    __syncthreads();

    // lane = oc (broadcast xs loads), warp = output row
    const int row = tid >> 5;   // 0..9
    const int oc  = lane;       // 0..31 (local)

    float wr[4][3][3];
#pragma unroll
    for (int ic = 0; ic < 4; ic++)
#pragma unroll
        for (int kh = 0; kh < 3; kh++)
#pragma unroll
            for (int kw = 0; kw < 3; kw++)
                wr[ic][kh][kw] = ws[oc * 37 + (ic * 3 + kh) * 3 + kw];
    const float bb = bias[oc];

    float y[8];
#pragma unroll
    for (int wc = 0; wc < 8; wc++) y[wc] = bb;

    // sliding-window: per (ic,kh) load the 10-float row once (5 x LDS.64).
#pragma unroll
    for (int ic = 0; ic < 4; ic++) {
#pragma unroll
        for (int kh = 0; kh < 3; kh++) {
            const float2* xrow = (const float2*)&xs[ic][row + kh][0];
            float x[10];
#pragma unroll
            for (int t = 0; t < 5; t++) {
                float2 v2 = xrow[t];
                x[2 * t]     = v2.x;
                x[2 * t + 1] = v2.y;
            }
#pragma unroll
            for (int wc = 0; wc < 8; wc++)
#pragma unroll
                for (int kw = 0; kw < 3; kw++)
                    y[wc] = fmaf(x[wc + kw], wr[ic][kh][kw], y[wc]);
        }
    }
    float acc = 0.0f;
#pragma unroll
    for (int wc = 0; wc < 8; wc++)
        acc += fmaxf(y[wc], 0.0f);
    psum[row][oc] = acc;
    __syncthreads();

    if (tid < 32) {
        float s = 0.0f;
#pragma unroll
        for (int r = 0; r < 10; r++)
            s += psum[r][tid];
        g_emb[img][half * 32 + tid] = s * (1.0f / 80.0f);
    }
    __syncthreads();   // stores issued

    if (blockIdx.x != 0) {
        if (tid == 0) {
            __threadfence();              // release our g_emb stores
            atomicAdd(&g_count, 1);
        }
        return;
    }

    // ---------------- Phase 2 (block 0 only): match ----------------
    if (tid == 0) {
        while (atomicAdd(&g_count, 0) != 127) { }   // proven L2-atomic poll
    }
    __syncthreads();
    __threadfence();   // acquire before reading g_emb

    // load embeddings into padded smem via float4 (bypass L1)
    for (int i = tid; i < 32 * 16; i += 320) {
        int r = i >> 4, c = i & 15;
        ve4[r * 17 + c] = __ldcg((const float4*)&g_emb[r][c * 4]);
        pe4[r * 17 + c] = __ldcg((const float4*)&g_emb[32 + r][c * 4]);
    }
    __syncthreads();

    // scores + stable descending rank, fully in registers.
    // warp w (0..7) handles patches 4w..4w+3; lane = position v.
    const int wid = tid >> 5;
    const unsigned full = 0xffffffffu;
    if (wid < 8) {
        const int v = lane;
#pragma unroll
        for (int pp = 0; pp < 4; pp++) {
            const int p = wid * 4 + pp;
            float s = 0.0f;
#pragma unroll
            for (int i = 0; i < 16; i++) {
                float4 a = pe4[p * 17 + i];   // broadcast within warp
                float4 b = ve4[v * 17 + i];   // conflict-free (stride 17 f4)
                s = fmaf(a.x, b.x, s);
                s = fmaf(a.y, b.y, s);
                s = fmaf(a.z, b.z, s);
                s = fmaf(a.w, b.w, s);
            }
            // rank among the 32 scores of patch p (stable, descending)
            const float my = s;
            int r = 0;
#pragma unroll
            for (int j = 0; j < 32; j++) {
                float o = __shfl_sync(full, s, j);
                r += (o > my) || (o == my && j < v);
            }
            pref[p][r] = v;
        }
    }
    __syncthreads();

    // Greedy assignment, warp 0, one lane per pid. Round-sequential semantics
    // == per-round min-pid-per-untaken-position (positions never free up).
    if (tid < 32) {
        const int pid = tid;
        unsigned taken = 0;
        int mypos = -1;
#pragma unroll 1
        for (int round = 0; round < 32; round++) {
            int cand = pref[pid][round];
            bool want = (mypos < 0) && !((taken >> cand) & 1u);
            unsigned want_mask = __ballot_sync(full, want);
            unsigned grp = __match_any_sync(full, cand) & want_mask;
            bool won = want && ((grp & ((1u << pid) - 1u)) == 0u);
            if (won) mypos = cand;
            taken |= __reduce_or_sync(full, won ? (1u << cand) : 0u);
            if (__ballot_sync(full, mypos < 0) == 0u) break;
        }
        out[pid] = (float)mypos;   // float32 output dtype
    }

    // reset counter for next replay (all 127 adds already observed)
    if (tid == 0) atomicExch(&g_count, 0);
}

extern "C" void kernel_launch(void* const* d_in, const int* in_sizes, int n_in,
                              void* d_out, int out_size)
{
    // Input identification. p_old_idx is the unique 32-element input:
    //   dict/insertion order: [v_latent, p_tensor, p_old_idx, v_w, v_b, p_w, p_b]
    //   alphabetical order:   [p_b, p_old_idx, p_tensor, p_w, v_b, v_latent, v_w]
    const float *v_latent, *p_tensor, *v_w, *v_b, *p_w, *p_b;
    if (n_in >= 7 && in_sizes[2] == 32) {
        v_latent = (const float*)d_in[0];
        p_tensor = (const float*)d_in[1];
        v_w      = (const float*)d_in[3];
        v_b      = (const float*)d_in[4];
        p_w      = (const float*)d_in[5];
        p_b      = (const float*)d_in[6];
    } else {
        p_b      = (const float*)d_in[0];
        p_tensor = (const float*)d_in[2];
        p_w      = (const float*)d_in[3];
        v_b      = (const float*)d_in[4];
        v_latent = (const float*)d_in[5];
        v_w      = (const float*)d_in[6];
    }
    float* out = (float*)d_out;

    fused_matcher_kernel<<<128, 320>>>(v_latent, p_tensor, v_w, v_b, p_w, p_b, out);
}

// round 16
// speedup vs baseline: 1.3801x; 1.1555x over previous
#include <cuda_runtime.h>
#include <cuda_bf16.h>

#define HIDDEN 64
#define N_POS 32

// embeddings: rows 0..31 = video positions, rows 32..63 = patches
__device__ float g_emb[64][HIDDEN];
__device__ int   g_count = 0;   // arrival ticket counter (reset by last block)

// ---------------------------------------------------------------------------
// Fused kernel: 128 blocks x 320 threads.  (R8 base; handoff = ticket)
//  Phase 1 (all blocks): half the output channels of conv(4->64,3x3,SAME)
//                        +ReLU+avgpool for one image. blockIdx: img*2+half.
//  Arrival: last block to take a ticket flows directly into phase 2.
//  Phase 2 (last block): scores+rank (register/shfl) -> greedy -> d_out.
//                        Phase 2 is byte-for-byte R8 (proven fast).
// ---------------------------------------------------------------------------
__global__ __launch_bounds__(320)
void fused_matcher_kernel(const float* __restrict__ v_latent,
                          const float* __restrict__ p_tensor,
                          const float* __restrict__ v_w,
                          const float* __restrict__ v_b,
                          const float* __restrict__ p_w,
                          const float* __restrict__ p_b,
                          float* __restrict__ out)
{
    // 16B alignment is REQUIRED: rows are read below as float2 (LDS.64).
    __shared__ __align__(16) float xs[4][12][10];  // zero-padded input
    __shared__ float ws[32 * 37];       // 32 oc x 36 weights, stride 37 (bank-free)
    __shared__ float psum[10][32];      // per-row partial sums
    __shared__ int   s_ticket;
    // match-phase smem (last block only)
    __shared__ float4 pe4[32 * 17];     // patch emb, 68-float row stride
    __shared__ float4 ve4[32 * 17];     // video emb, 68-float row stride
    __shared__ int    pref[32][32];

    const int img  = blockIdx.x >> 1;
    const int half = blockIdx.x & 1;    // which 32 output channels
    const bool is_v = img < 32;
    const float* __restrict__ w    = (is_v ? v_w : p_w) + half * 32 * 36;
    const float* __restrict__ bias = (is_v ? v_b : p_b) + half * 32;
    const int tid  = threadIdx.x;
    const int lane = tid & 31;

    // ---------------- Phase 1: conv + relu + avgpool (R8-proven) ----------
    for (int i = tid; i < 4 * 12 * 10; i += 320)
        ((float*)xs)[i] = 0.0f;
    for (int i = tid; i < 32 * 36; i += 320)
        ws[(i / 36) * 37 + (i % 36)] = w[i];
    __syncthreads();

    // interior: logical x[a][c][e], a=ch(4), c=h(10), e=w(8)
    {
        int i = tid;   // 320 threads == 320 elements
        int e = i & 7;
        int c = (i >> 3) % 10;
        int a = i / 80;
        float val;
        if (is_v) {
            // v_split[pos=b*8+d, a, c, e] = v_latent[a, b, c, d, e]
            int b_ = img >> 3, d = img & 7;
            val = v_latent[(((a * 4 + b_) * 10 + c) * 8 + d) * 8 + e];
        } else {
            val = p_tensor[(img - 32) * 320 + i];
        }
        xs[a][c + 1][e + 1] = val;
    }
    __syncthreads();

    // lane = oc (broadcast xs loads), warp = output row
    const int row = tid >> 5;   // 0..9
    const int oc  = lane;       // 0..31 (local)

    float wr[4][3][3];
#pragma unroll
    for (int ic = 0; ic < 4; ic++)
#pragma unroll
        for (int kh = 0; kh < 3; kh++)
#pragma unroll
            for (int kw = 0; kw < 3; kw++)
                wr[ic][kh][kw] = ws[oc * 37 + (ic * 3 + kh) * 3 + kw];
    const float bb = bias[oc];

    float y[8];
#pragma unroll
    for (int wc = 0; wc < 8; wc++) y[wc] = bb;

    // sliding-window: per (ic,kh) load the 10-float row once (5 x LDS.64).
#pragma unroll
    for (int ic = 0; ic < 4; ic++) {
#pragma unroll
        for (int kh = 0; kh < 3; kh++) {
            const float2* xrow = (const float2*)&xs[ic][row + kh][0];
            float x[10];
#pragma unroll
            for (int t = 0; t < 5; t++) {
                float2 v2 = xrow[t];
                x[2 * t]     = v2.x;
                x[2 * t + 1] = v2.y;
            }
#pragma unroll
            for (int wc = 0; wc < 8; wc++)
#pragma unroll
                for (int kw = 0; kw < 3; kw++)
                    y[wc] = fmaf(x[wc + kw], wr[ic][kh][kw], y[wc]);
        }
    }
    float acc = 0.0f;
#pragma unroll
    for (int wc = 0; wc < 8; wc++)
        acc += fmaxf(y[wc], 0.0f);
    psum[row][oc] = acc;
    __syncthreads();

    if (tid < 32) {
        float s = 0.0f;
#pragma unroll
        for (int r = 0; r < 10; r++)
            s += psum[r][tid];
        g_emb[img][half * 32 + tid] = s * (1.0f / 80.0f);
    }
    __syncthreads();   // stores issued

    // ------------- arrival: last block to take a ticket runs phase 2 ------
    if (tid == 0) {
        __threadfence();                       // release our g_emb stores
        s_ticket = atomicAdd(&g_count, 1);
    }
    __syncthreads();
    if (s_ticket != 127)
        return;                                 // not last: done

    __threadfence();   // acquire: order g_emb reads after the atomic

    // reset counter for next replay (all 128 adds already observed)
    if (tid == 0) atomicExch(&g_count, 0);

    // ---------------- Phase 2 (last block): match — byte-for-byte R8 ------
    // load embeddings into padded smem via float4 (bypass L1)
    for (int i = tid; i < 32 * 16; i += 320) {
        int r = i >> 4, c = i & 15;
        ve4[r * 17 + c] = __ldcg((const float4*)&g_emb[r][c * 4]);
        pe4[r * 17 + c] = __ldcg((const float4*)&g_emb[32 + r][c * 4]);
    }
    __syncthreads();

    // scores + stable descending rank, fully in registers.
    // warp w (0..7) handles patches 4w..4w+3; lane = position v.
    const int wid = tid >> 5;
    const unsigned full = 0xffffffffu;
    if (wid < 8) {
        const int v = lane;
#pragma unroll
        for (int pp = 0; pp < 4; pp++) {
            const int p = wid * 4 + pp;
            float s = 0.0f;
#pragma unroll
            for (int i = 0; i < 16; i++) {
                float4 a = pe4[p * 17 + i];   // broadcast within warp
                float4 b = ve4[v * 17 + i];   // conflict-free (stride 17 f4)
                s = fmaf(a.x, b.x, s);
                s = fmaf(a.y, b.y, s);
                s = fmaf(a.z, b.z, s);
                s = fmaf(a.w, b.w, s);
            }
            // rank among the 32 scores of patch p (stable, descending)
            const float my = s;
            int r = 0;
#pragma unroll
            for (int j = 0; j < 32; j++) {
                float o = __shfl_sync(full, s, j);
                r += (o > my) || (o == my && j < v);
            }
            pref[p][r] = v;
        }
    }
    __syncthreads();

    // Greedy assignment, warp 0, one lane per pid. Round-sequential semantics
    // == per-round min-pid-per-untaken-position (positions never free up).
    // (R8's exact 4-collective form — the 2-collective variant measured slower.)
    if (tid < 32) {
        const int pid = tid;
        unsigned taken = 0;
        int mypos = -1;
#pragma unroll 1
        for (int round = 0; round < 32; round++) {
            int cand = pref[pid][round];
            bool want = (mypos < 0) && !((taken >> cand) & 1u);
            unsigned want_mask = __ballot_sync(full, want);
            unsigned grp = __match_any_sync(full, cand) & want_mask;
            bool won = want && ((grp & ((1u << pid) - 1u)) == 0u);
            if (won) mypos = cand;
            taken |= __reduce_or_sync(full, won ? (1u << cand) : 0u);
            if (__ballot_sync(full, mypos < 0) == 0u) break;
        }
        out[pid] = (float)mypos;   // float32 output dtype
    }
}

extern "C" void kernel_launch(void* const* d_in, const int* in_sizes, int n_in,
                              void* d_out, int out_size)
{
    // Input identification. p_old_idx is the unique 32-element input:
    //   dict/insertion order: [v_latent, p_tensor, p_old_idx, v_w, v_b, p_w, p_b]
    //   alphabetical order:   [p_b, p_old_idx, p_tensor, p_w, v_b, v_latent, v_w]
    const float *v_latent, *p_tensor, *v_w, *v_b, *p_w, *p_b;
    if (n_in >= 7 && in_sizes[2] == 32) {
        v_latent = (const float*)d_in[0];
        p_tensor = (const float*)d_in[1];
        v_w      = (const float*)d_in[3];
        v_b      = (const float*)d_in[4];
        p_w      = (const float*)d_in[5];
        p_b      = (const float*)d_in[6];
    } else {
        p_b      = (const float*)d_in[0];
        p_tensor = (const float*)d_in[2];
        p_w      = (const float*)d_in[3];
        v_b      = (const float*)d_in[4];
        v_latent = (const float*)d_in[5];
        v_w      = (const float*)d_in[6];
    }
    float* out = (float*)d_out;

    fused_matcher_kernel<<<128, 320>>>(v_latent, p_tensor, v_w, v_b, p_w, p_b, out);
}